// round 1
// baseline (speedup 1.0000x reference)
#include <cuda_runtime.h>
#include <math.h>

#define AN 5
#define NCL 20
#define FD 38
#define SS (FD*FD)
#define MAXB 32
#define MAXO 64
#define IGN 0.6f
#define NSA (AN*SS)

// ---------------- scratch (device globals; no allocation) ----------------
__device__ float  g_maxiou[MAXB*NSA];
__device__ float4 g_boxt  [MAXB*NSA];
__device__ float  g_clst  [MAXB*NSA];
__device__ float  g_iout  [MAXB*NSA];
__device__ float  g_mask  [MAXB*NSA];
__device__ int    g_npos  [MAXB];

__device__ __forceinline__ float sigf(float x) { return 1.0f / (1.0f + expf(-x)); }

// ---------------- K0: zero per-launch state ----------------
__global__ void k_init(float* out, int B) {
    int t = threadIdx.x;
    if (t < B) g_npos[t] = 0;
    if (t == 0) out[0] = 0.0f;
}

// ---------------- K1: per (b,a,s) pred box -> max IoU vs valid GTs ----------------
__global__ void k_maxiou(const float* __restrict__ outp,
                         const float* __restrict__ tgt,
                         const float* __restrict__ anch,
                         int B, int O)
{
    int b = blockIdx.y;
    __shared__ float sx1[MAXO], sy1[MAXO], sx2[MAXO], sy2[MAXO], sar[MAXO];
    __shared__ int snv;
    if (threadIdx.x == 0) snv = 0;
    __syncthreads();
    // compact valid GTs into smem (order-independent: only max is taken)
    for (int o = threadIdx.x; o < O; o += blockDim.x) {
        const float* tr = tgt + (size_t)(b*O + o)*5;
        float cx = tr[0], cy = tr[1], w = tr[2], h = tr[3], cl = tr[4];
        if (cx + cy + w + h + cl > 0.0f) {
            int k = atomicAdd(&snv, 1);
            float gx = cx*FD, gy = cy*FD, gw = w*FD, gh = h*FD;
            sx1[k] = gx - gw*0.5f; sy1[k] = gy - gh*0.5f;
            sx2[k] = gx + gw*0.5f; sy2[k] = gy + gh*0.5f;
            sar[k] = gw*gh;
        }
    }
    __syncthreads();
    int nv = snv;

    int sa = blockIdx.x*blockDim.x + threadIdx.x;
    if (sa >= NSA) return;
    int a = sa / SS, s = sa % SS;
    int j = s % FD, i = s / FD;

    const float* ob = outp + ((size_t)(b*AN + a)*(5+NCL))*SS + s;
    float tx = ob[0], ty = ob[SS], tw = ob[2*SS], th = ob[3*SS];
    float aw = anch[2*a]*FD, ah = anch[2*a+1]*FD;
    float px = sigf(tx) + (float)j;
    float py = sigf(ty) + (float)i;
    float pw = expf(tw)*aw, ph = expf(th)*ah;
    float px1 = px - pw*0.5f, py1 = py - ph*0.5f;
    float px2 = px + pw*0.5f, py2 = py + ph*0.5f;
    float pa = pw*ph + 1e-12f;

    // track max IoU as a fraction; compare via cross-multiplication (no divs in loop)
    float bi = 0.0f, bu = 1.0f;
    #pragma unroll 2
    for (int o = 0; o < nv; o++) {
        float ix = fminf(px2, sx2[o]) - fmaxf(px1, sx1[o]);
        float iy = fminf(py2, sy2[o]) - fmaxf(py1, sy1[o]);
        ix = fmaxf(ix, 0.0f); iy = fmaxf(iy, 0.0f);
        float inter = ix*iy;
        float uni = (pa + sar[o]) - inter;
        if (inter*bu > bi*uni) { bi = inter; bu = uni; }
    }
    float mi = bi / bu;

    int idx = (b*AN + a)*SS + s;
    g_maxiou[idx] = mi;
    g_mask[idx] = 0.0f; g_clst[idx] = 0.0f; g_iout[idx] = 0.0f;
    g_boxt[idx] = make_float4(0.f, 0.f, 0.f, 0.f);
    if (mi > IGN) atomicOr(&g_npos[b], 1);
}

// ---------------- K2: per-batch serial object assignment (last write wins) ----------------
__global__ void k_assign(const float* __restrict__ tgt,
                         const float* __restrict__ anch,
                         int B, int O)
{
    int b = blockIdx.x*blockDim.x + threadIdx.x;
    if (b >= B) return;
    for (int o = 0; o < O; o++) {
        const float* tr = tgt + (size_t)(b*O + o)*5;
        float cx = tr[0], cy = tr[1], w = tr[2], h = tr[3], cl = tr[4];
        if (!(cx + cy + w + h + cl > 0.0f)) continue;   // invalid -> dropped
        float gx = cx*FD, gy = cy*FD, gw = w*FD, gh = h*FD;
        float x1 = gx - gw*0.5f, y1 = gy - gh*0.5f;
        float gx2 = gx + gw*0.5f, gy2 = gy + gh*0.5f;
        int ci = (int)floorf(x1), cj = (int)floorf(y1);
        int cell = cj*FD + ci;
        cell = min(max(cell, 0), SS - 1);
        float ax = (float)(cell % FD) + 0.5f;
        float ay = (float)(cell / FD) + 0.5f;
        float ga = gw*gh;
        // argmax over anchors (first max wins, like jnp.argmax)
        float best = -1.0f; int ba = 0;
        for (int a = 0; a < AN; a++) {
            float aw = anch[2*a]*FD, ah = anch[2*a+1]*FD;
            float ix = fminf(ax + aw*0.5f, gx2) - fmaxf(ax - aw*0.5f, x1);
            float iy = fminf(ay + ah*0.5f, gy2) - fmaxf(ay - ah*0.5f, y1);
            ix = fmaxf(ix, 0.0f); iy = fmaxf(iy, 0.0f);
            float inter = ix*iy;
            float iou = inter / (aw*ah + ga - inter + 1e-12f);
            if (iou > best) { best = iou; ba = a; }
        }
        float raw = anch[2*ba]*FD, rah = anch[2*ba+1]*FD;
        int idx = (b*AN + ba)*SS + cell;
        g_boxt[idx] = make_float4(gx - ax, gy - ay, gw / raw, gh / rah);
        g_mask[idx] = 1.0f;
        g_clst[idx] = cl;
        g_iout[idx] = g_maxiou[idx];
    }
}

// ---------------- K3: loss reduction ----------------
__global__ void k_loss(const float* __restrict__ outp, float* out, int B)
{
    int b = blockIdx.y;
    int sa = blockIdx.x*blockDim.x + threadIdx.x;
    float acc = 0.0f;
    if (sa < NSA) {
        int a = sa / SS, s = sa % SS;
        int idx = (b*AN + a)*SS + s;
        const float* ob = outp + ((size_t)(b*AN + a)*(5+NCL))*SS + s;
        float conf = sigf(ob[4*SS]);
        float msk = g_mask[idx];
        float mi  = g_maxiou[idx];
        int   np  = g_npos[b];
        float im  = (msk > 0.0f) ? 5.0f : ((np && mi >= IGN) ? 0.0f : 1.0f);
        float it  = g_iout[idx];
        float d   = conf*im - it*im;
        acc = d*d;
        if (msk > 0.0f) {
            float4 bt = g_boxt[idx];
            float dx = sigf(ob[0])     - bt.x;
            float dy = sigf(ob[SS])    - bt.y;
            float dw = expf(ob[2*SS])  - bt.z;
            float dh = expf(ob[3*SS])  - bt.w;
            acc += dx*dx + dy*dy + dw*dw + dh*dh;
            // class: ce = -log_softmax(softmax(z))[ct], replicated exactly
            float z[NCL];
            float m = -1e30f;
            #pragma unroll
            for (int c = 0; c < NCL; c++) { z[c] = ob[(5 + c)*SS]; m = fmaxf(m, z[c]); }
            float se = 0.0f;
            #pragma unroll
            for (int c = 0; c < NCL; c++) { z[c] = expf(z[c] - m); se += z[c]; }
            float inv = 1.0f / se;
            float pm = -1e30f;
            #pragma unroll
            for (int c = 0; c < NCL; c++) { z[c] *= inv; pm = fmaxf(pm, z[c]); }
            float se2 = 0.0f;
            #pragma unroll
            for (int c = 0; c < NCL; c++) se2 += expf(z[c] - pm);
            int ct = (int)g_clst[idx];
            acc += pm + logf(se2) - z[ct];
        }
    }
    __shared__ float red[256];
    red[threadIdx.x] = acc;
    __syncthreads();
    for (int st = 128; st > 0; st >>= 1) {
        if (threadIdx.x < st) red[threadIdx.x] += red[threadIdx.x + st];
        __syncthreads();
    }
    if (threadIdx.x == 0) atomicAdd(out, red[0] / (float)B);
}

// ---------------- launch ----------------
extern "C" void kernel_launch(void* const* d_in, const int* in_sizes, int n_in,
                              void* d_out, int out_size)
{
    const float* outp = (const float*)d_in[0];
    const float* tgt  = (const float*)d_in[1];
    const float* anch = (const float*)d_in[2];
    int B = in_sizes[0] / (AN*(5+NCL)*SS);
    int O = in_sizes[1] / (B*5);
    float* out = (float*)d_out;

    k_init<<<1, 256>>>(out, B);
    dim3 grid((NSA + 255)/256, B);
    k_maxiou<<<grid, 256>>>(outp, tgt, anch, B, O);
    k_assign<<<1, 32>>>(tgt, anch, B, O);
    k_loss<<<grid, 256>>>(outp, out, B);
}

// round 2
// speedup vs baseline: 1.1866x; 1.1866x over previous
#include <cuda_runtime.h>
#include <math.h>

#define AN 5
#define NCL 20
#define FD 38
#define SS 1444            // FD*FD
#define MAXB 32
#define MAXO 64
#define IGN 0.6f
#define NSA (AN*SS)        // 7220
#define QP (NSA/4)         // 1805 threads per batch (4 positions each)

// ---------------- scratch (device globals; no allocation) ----------------
__device__ float         g_maxiou[MAXB*NSA];
__device__ unsigned char g_tag   [MAXB*NSA];
__device__ int           g_npos  [MAXB];

__device__ __forceinline__ float sigf(float x) { return 1.0f / (1.0f + expf(-x)); }

// ---------------- K0: zero per-launch state ----------------
__global__ void k_init(float* out) {
    int t = threadIdx.x;
    if (t < MAXB) g_npos[t] = 0;
    if (t == 0) out[0] = 0.0f;
}

// ---------------- K1: max IoU per pred box (4 positions/thread) ----------------
__global__ void __launch_bounds__(256) k_maxiou(const float* __restrict__ outp,
                                                const float* __restrict__ tgt,
                                                const float* __restrict__ anch,
                                                int B, int O)
{
    int b = blockIdx.y;
    __shared__ float sx1[MAXO], sy1[MAXO], sx2[MAXO], sy2[MAXO], sar[MAXO];
    __shared__ int snv;
    if (threadIdx.x == 0) snv = 0;
    __syncthreads();
    // compact valid GTs into smem (order-independent: only max is taken)
    for (int o = threadIdx.x; o < O; o += blockDim.x) {
        const float* tr = tgt + (size_t)(b*O + o)*5;
        float cx = tr[0], cy = tr[1], w = tr[2], h = tr[3], cl = tr[4];
        if (cx + cy + w + h + cl > 0.0f) {
            int k = atomicAdd(&snv, 1);
            float gx = cx*FD, gy = cy*FD, gw = w*FD, gh = h*FD;
            sx1[k] = gx - gw*0.5f; sy1[k] = gy - gh*0.5f;
            sx2[k] = gx + gw*0.5f; sy2[k] = gy + gh*0.5f;
            sar[k] = gw*gh;
        }
    }
    __syncthreads();
    int nv = snv;

    int q = blockIdx.x*blockDim.x + threadIdx.x;
    if (q >= QP) return;
    int sa = q*4;                       // SS%4==0 -> all 4 positions share anchor a
    int a = sa / SS, s = sa - a*SS;

    const float* ob = outp + ((size_t)(b*AN + a)*(5+NCL))*SS + s;
    float4 tx = *(const float4*)(ob);
    float4 ty = *(const float4*)(ob + SS);
    float4 tw = *(const float4*)(ob + 2*SS);
    float4 th = *(const float4*)(ob + 3*SS);
    float aw = anch[2*a]*FD, ah = anch[2*a+1]*FD;

    float px1[4], px2[4], py1[4], py2[4], pa[4], bi[4], bS[4];
    int j0 = s % FD, i0 = s / FD;
    #pragma unroll
    for (int k = 0; k < 4; k++) {
        int j = j0 + k, i = i0;
        if (j >= FD) { j -= FD; i += 1; }
        float cxp = sigf((&tx.x)[k]) + (float)j;
        float cyp = sigf((&ty.x)[k]) + (float)i;
        float pw = expf((&tw.x)[k])*aw;
        float ph = expf((&th.x)[k])*ah;
        px1[k] = cxp - pw*0.5f; px2[k] = cxp + pw*0.5f;
        py1[k] = cyp - ph*0.5f; py2[k] = cyp + ph*0.5f;
        pa[k] = pw*ph + 1e-12f;
        bi[k] = 0.0f; bS[k] = 1.0f;
    }

    // track (inter, S); IoU = inter/(S - inter) monotone in inter/S -> cross-mult compare
    #pragma unroll 2
    for (int o = 0; o < nv; o++) {
        float gx1 = sx1[o], gy1 = sy1[o], gx2 = sx2[o], gy2 = sy2[o], ga = sar[o];
        #pragma unroll
        for (int k = 0; k < 4; k++) {
            float ix = fminf(px2[k], gx2) - fmaxf(px1[k], gx1);
            float iy = fminf(py2[k], gy2) - fmaxf(py1[k], gy1);
            float inter = fmaxf(ix, 0.0f) * fmaxf(iy, 0.0f);
            float S = pa[k] + ga;
            if (inter*bS[k] > bi[k]*S) { bi[k] = inter; bS[k] = S; }
        }
    }

    float4 mi4;
    int anyp = 0;
    #pragma unroll
    for (int k = 0; k < 4; k++) {
        float mi = bi[k] / (bS[k] - bi[k]);
        (&mi4.x)[k] = mi;
        if (mi > IGN) anyp = 1;
    }
    int idx = b*NSA + sa;
    *(float4*)(g_maxiou + idx) = mi4;
    *(uchar4*)(g_tag + idx) = make_uchar4(0,0,0,0);
    if (anyp) atomicOr(&g_npos[b], 1);
}

// ---------------- K2: parallel assignment + box/class loss ----------------
// winner per (cell,anchor) = highest object index (last-write-wins semantics)
__global__ void k_assign(const float* __restrict__ outp,
                         const float* __restrict__ tgt,
                         const float* __restrict__ anch,
                         float* out, int B, int O)
{
    int b = blockIdx.x;
    int o = threadIdx.x;                 // blockDim = 64 >= O
    __shared__ int  sidx[MAXO];
    __shared__ float sred[64];

    int myidx = -1, mya = 0;
    float gx = 0.f, gy = 0.f, gw = 0.f, gh = 0.f, cl = 0.f, ax = 0.f, ay = 0.f;
    if (o < O) {
        const float* tr = tgt + (size_t)(b*O + o)*5;
        float cx = tr[0], cyy = tr[1], w = tr[2], h = tr[3]; cl = tr[4];
        if (cx + cyy + w + h + cl > 0.0f) {
            gx = cx*FD; gy = cyy*FD; gw = w*FD; gh = h*FD;
            float x1 = gx - gw*0.5f, y1 = gy - gh*0.5f;
            float x2 = gx + gw*0.5f, y2 = gy + gh*0.5f;
            int ci = (int)floorf(x1), cj = (int)floorf(y1);
            int cell = min(max(cj*FD + ci, 0), SS - 1);
            ax = (float)(cell % FD) + 0.5f;
            ay = (float)(cell / FD) + 0.5f;
            float ga = gw*gh;
            float best = -1.0f; int ba = 0;
            #pragma unroll
            for (int a2 = 0; a2 < AN; a2++) {
                float aw = anch[2*a2]*FD, ah = anch[2*a2+1]*FD;
                float ix = fminf(ax + aw*0.5f, x2) - fmaxf(ax - aw*0.5f, x1);
                float iy = fminf(ay + ah*0.5f, y2) - fmaxf(ay - ah*0.5f, y1);
                float inter = fmaxf(ix, 0.0f)*fmaxf(iy, 0.0f);
                float iou = inter / (aw*ah + ga - inter + 1e-12f);
                if (iou > best) { best = iou; ba = a2; }
            }
            mya = ba;
            myidx = (b*AN + ba)*SS + cell;
        }
    }
    sidx[threadIdx.x] = (o < O) ? myidx : -1;
    __syncthreads();

    bool win = (myidx >= 0);
    if (win) {
        for (int o2 = o + 1; o2 < O; o2++)
            if (sidx[o2] == myidx) { win = false; break; }
    }

    float acc = 0.0f;
    if (win) {
        g_tag[myidx] = 1;
        int cell = myidx % SS;
        const float* ob = outp + ((size_t)(b*AN + mya)*(5+NCL))*SS + cell;
        float raw = anch[2*mya]*FD, rah = anch[2*mya+1]*FD;
        float dx = sigf(ob[0])    - (gx - ax);
        float dy = sigf(ob[SS])   - (gy - ay);
        float dw = expf(ob[2*SS]) - gw/raw;
        float dh = expf(ob[3*SS]) - gh/rah;
        acc = dx*dx + dy*dy + dw*dw + dh*dh;
        // class CE = -log_softmax(softmax(z))[ct], replicated exactly
        float z[NCL];
        float m = -1e30f;
        #pragma unroll
        for (int c = 0; c < NCL; c++) { z[c] = ob[(5 + c)*SS]; m = fmaxf(m, z[c]); }
        float se = 0.0f;
        #pragma unroll
        for (int c = 0; c < NCL; c++) { z[c] = expf(z[c] - m); se += z[c]; }
        float inv = 1.0f/se;
        float pm = -1e30f;
        #pragma unroll
        for (int c = 0; c < NCL; c++) { z[c] *= inv; pm = fmaxf(pm, z[c]); }
        float se2 = 0.0f;
        #pragma unroll
        for (int c = 0; c < NCL; c++) se2 += expf(z[c] - pm);
        int ct = (int)cl;
        acc += pm + logf(se2) - z[ct];
    }

    sred[threadIdx.x] = acc;
    __syncthreads();
    for (int st = 32; st > 0; st >>= 1) {
        if (threadIdx.x < st) sred[threadIdx.x] += sred[threadIdx.x + st];
        __syncthreads();
    }
    if (threadIdx.x == 0 && sred[0] != 0.0f)
        atomicAdd(out, sred[0] / (float)B);
}

// ---------------- K3: confidence loss (4 positions/thread) ----------------
__global__ void __launch_bounds__(256) k_loss(const float* __restrict__ outp,
                                              float* out, int B)
{
    int b = blockIdx.y;
    int q = blockIdx.x*blockDim.x + threadIdx.x;
    float acc = 0.0f;
    if (q < QP) {
        int sa = q*4;
        int a = sa / SS, s = sa - a*SS;
        const float* cb = outp + ((size_t)(b*AN + a)*(5+NCL) + 4)*SS + s;
        float4 c4 = *(const float4*)cb;
        int idx = b*NSA + sa;
        float4 m4 = *(const float4*)(g_maxiou + idx);
        uchar4 t4 = *(const uchar4*)(g_tag + idx);
        int np = g_npos[b];
        #pragma unroll
        for (int k = 0; k < 4; k++) {
            float conf = sigf((&c4.x)[k]);
            float mi = (&m4.x)[k];
            unsigned char tg = (&t4.x)[k];
            float im = tg ? 5.0f : ((np && mi >= IGN) ? 0.0f : 1.0f);
            float it = tg ? mi : 0.0f;
            float d = (conf - it)*im;
            acc += d*d;
        }
    }
    __shared__ float red[256];
    red[threadIdx.x] = acc;
    __syncthreads();
    for (int st = 128; st > 0; st >>= 1) {
        if (threadIdx.x < st) red[threadIdx.x] += red[threadIdx.x + st];
        __syncthreads();
    }
    if (threadIdx.x == 0) atomicAdd(out, red[0] / (float)B);
}

// ---------------- launch ----------------
extern "C" void kernel_launch(void* const* d_in, const int* in_sizes, int n_in,
                              void* d_out, int out_size)
{
    const float* outp = (const float*)d_in[0];
    const float* tgt  = (const float*)d_in[1];
    const float* anch = (const float*)d_in[2];
    int B = in_sizes[0] / (AN*(5+NCL)*SS);
    int O = in_sizes[1] / (B*5);
    float* out = (float*)d_out;

    k_init<<<1, 32>>>(out);
    dim3 grid((QP + 255)/256, B);
    k_maxiou<<<grid, 256>>>(outp, tgt, anch, B, O);
    k_assign<<<B, 64>>>(outp, tgt, anch, out, B, O);
    k_loss<<<grid, 256>>>(outp, out, B);
}